// round 14
// baseline (speedup 1.0000x reference)
#include <cuda_runtime.h>
#include <cuda_fp16.h>
#include <math.h>
#include <stdint.h>

#define N_NODES  50000
#define N_EDGES  800000
#define N_GRAPHS 512
#define HID      128
#define RBF      32
#define NLAYERS  6
#define GAMMA    32.0f

// LUT parameters: W(d) sampled on [0, SPAN], clamped above (rbf ~ 0 beyond)
#define NK       2048
#define SPAN     6.4f
#define LSTEP    (SPAN / (NK - 1))
#define INV_STEP ((NK - 1) / SPAN)

// ================= scratch (static device globals; no allocation) =================
__device__ __align__(16) __half g_hh[(size_t)N_NODES * HID];     // node features fp16
__device__ float g_aggr[(size_t)N_NODES * HID];
__device__ float g_deg[N_NODES];
__device__ float g_d[N_EDGES];                                   // edge distances
__device__ __align__(16) float g_lut[NLAYERS * NK * HID];        // 6.3 MB fp32 W(d) tables
__device__ __align__(16) __half g_uw1t[NLAYERS * HID * HID];
__device__ __align__(16) __half g_uw2t[NLAYERS * HID * HID];     // rows PERMUTED
__device__ __align__(16) __half g_ow1t[HID * HID];
__device__ __align__(16) __half g_ow2t[HID * HID];               // rows PERMUTED

// permutation of second-GEMM B rows within each 32-block:
// physical row (ni*8 + tq*2 + b) holds logical channel (tq*8 + ni*2 + b)
__host__ __device__ __forceinline__ int permL(int n) {
    return (n & ~31) | ((((n >> 1) & 3) << 3) | (((n >> 3) & 3) << 1) | (n & 1));
}

// ================= helpers =================
__device__ __forceinline__ float sspf(float x) {
    return fmaxf(x, 0.0f) + __logf(1.0f + __expf(-fabsf(x))) - 0.5f;
}
__device__ __forceinline__ void red4(float* p, float a, float b, float c, float d) {
    asm volatile("red.global.add.v4.f32 [%0], {%1,%2,%3,%4};"
                 :: "l"(p), "f"(a), "f"(b), "f"(c), "f"(d) : "memory");
}
__device__ __forceinline__ void mma16816(float c[4], uint32_t a0, uint32_t a1,
                                         uint32_t a2, uint32_t a3,
                                         uint32_t b0, uint32_t b1) {
    asm volatile(
        "mma.sync.aligned.m16n8k16.row.col.f32.f16.f16.f32 "
        "{%0,%1,%2,%3}, {%4,%5,%6,%7}, {%8,%9}, {%0,%1,%2,%3};"
        : "+f"(c[0]), "+f"(c[1]), "+f"(c[2]), "+f"(c[3])
        : "r"(a0), "r"(a1), "r"(a2), "r"(a3), "r"(b0), "r"(b1));
}
__device__ __forceinline__ void ldsm_x4(uint32_t (&r)[4], uint32_t addr) {
    asm volatile("ldmatrix.sync.aligned.m8n8.x4.shared.b16 {%0,%1,%2,%3}, [%4];"
                 : "=r"(r[0]), "=r"(r[1]), "=r"(r[2]), "=r"(r[3]) : "r"(addr));
}
__device__ __forceinline__ uint32_t smem_u32(const void* p) {
    uint32_t a;
    asm("{ .reg .u64 t; cvta.to.shared.u64 t, %1; cvt.u32.u64 %0, t; }" : "=r"(a) : "l"(p));
    return a;
}

template<int STRIDE, int NKT>
__device__ __forceinline__ void gemm_ldsm(uint32_t aBase, uint32_t bBase,
                                          float (&acc)[4][4][4])
{
#pragma unroll
    for (int mi = 0; mi < 4; mi++)
#pragma unroll
        for (int ni = 0; ni < 4; ni++)
#pragma unroll
            for (int q = 0; q < 4; q++) acc[mi][ni][q] = 0.0f;
#pragma unroll
    for (int kt = 0; kt < NKT; kt++) {
        const int kb = kt * 32;
        uint32_t B[2][4];
        ldsm_x4(B[0], bBase + kb);
        ldsm_x4(B[1], bBase + 16 * STRIDE + kb);
        uint32_t A[4][4];
#pragma unroll
        for (int mi = 0; mi < 4; mi++)
            ldsm_x4(A[mi], aBase + mi * 16 * STRIDE + kb);
#pragma unroll
        for (int mi = 0; mi < 4; mi++)
#pragma unroll
            for (int ni = 0; ni < 4; ni++)
                mma16816(acc[mi][ni], A[mi][0], A[mi][1], A[mi][2], A[mi][3],
                         B[ni >> 1][(ni & 1) * 2], B[ni >> 1][(ni & 1) * 2 + 1]);
    }
}

__device__ __forceinline__ void store_t_ssp(char* sm, int offT,
                                            const float (&acc)[4][4][4],
                                            const float* s_b,
                                            int erow0, int nbase, int rlo, int tq)
{
#pragma unroll
    for (int mi = 0; mi < 4; mi++) {
        int r = erow0 + mi * 16 + rlo;
#pragma unroll
        for (int ni = 0; ni < 4; ni++) {
            int col = nbase + ni * 8 + tq * 2;
            float b0 = s_b[col], b1 = s_b[col + 1];
            __half2 lo = __floats2half2_rn(sspf(acc[mi][ni][0] + b0),
                                           sspf(acc[mi][ni][1] + b1));
            __half2 hi = __floats2half2_rn(sspf(acc[mi][ni][2] + b0),
                                           sspf(acc[mi][ni][3] + b1));
            *(__half2*)(sm + offT + r * 272 + col * 2) = lo;
            *(__half2*)(sm + offT + (r + 8) * 272 + col * 2) = hi;
        }
    }
}

// ================= setup (exactly 3 launches before first edge kernel) =================
// launch 1: h init + zero aggr/deg/out
__global__ void k_setup(const int* __restrict__ z, const float* __restrict__ embed,
                        float* __restrict__ out) {
    int idx = blockIdx.x * blockDim.x + threadIdx.x;
    if (idx < N_NODES * HID) {
        int n = idx >> 7, c = idx & 127;
        g_hh[idx] = __float2half(embed[z[n] * HID + c]);
        g_aggr[idx] = 0.0f;
    }
    if (idx < N_NODES) g_deg[idx] = 0.0f;
    if (idx < N_GRAPHS) out[idx] = 0.0f;
}

// launch 2: distances + degree count
__global__ void k_dist(const int* __restrict__ gI, const int* __restrict__ gJ,
                       const float* __restrict__ pos) {
    int e = blockIdx.x * blockDim.x + threadIdx.x;
    if (e >= N_EDGES) return;
    int i = gI[e], j = gJ[e];
    float dx = pos[i * 3 + 0] - pos[j * 3 + 0];
    float dy = pos[i * 3 + 1] - pos[j * 3 + 1];
    float dz = pos[i * 3 + 2] - pos[j * 3 + 2];
    g_d[e] = sqrtf(dx * dx + dy * dy + dz * dz);
    atomicAdd(&g_deg[i], 1.0f);
}

// launch 3: LUT build (blocks 0..767) + node/output weight prep + invdeg (rest)
#define LUT_BLOCKS 768      // 6 layers x 128 blocks x 16 knots
#define PREP_TOTAL (98304 * 2 + 16384 * 2 + N_NODES)   // 279376
#define PREP_BLOCKS ((PREP_TOTAL + 127) / 128)         // 2183

__global__ void k_prep(const float* __restrict__ fw1, const float* __restrict__ fb1,
                       const float* __restrict__ fw2, const float* __restrict__ fb2,
                       const float* __restrict__ uw1, const float* __restrict__ uw2,
                       const float* __restrict__ ow1, const float* __restrict__ ow2) {
    const int b = blockIdx.x;
    const int tid = threadIdx.x;
    if (b < LUT_BLOCKS) {
        const int l = b >> 7;                 // layer
        const int kb = (b & 127) * 16;        // first knot of this block
        __shared__ float s_rbf[32];
        __shared__ float s_t[128];
        for (int kk = 0; kk < 16; kk++) {
            const int knot = kb + kk;
            const float d = knot * LSTEP;
            if (tid < 32) {
                float u = d - tid * (4.0f / 31.0f);
                s_rbf[tid] = expf(-GAMMA * u * u);
            }
            __syncthreads();
            float acc = fb1[l * HID + tid];
            for (int k2 = 0; k2 < RBF; k2++)
                acc = fmaf(s_rbf[k2], fw1[l * RBF * HID + k2 * HID + tid], acc);
            s_t[tid] = sspf(acc);
            __syncthreads();
            float wv = fb2[l * HID + tid];
            for (int j = 0; j < HID; j++)
                wv = fmaf(s_t[j], fw2[l * HID * HID + j * HID + tid], wv);
            g_lut[((size_t)l * NK + knot) * HID + tid] = wv;
            __syncthreads();
        }
        return;
    }
    int idx = (b - LUT_BLOCKS) * 128 + tid;
    if (idx < 98304) {                        // uw1t natural
        int l = idx >> 14, rem = idx & 16383, n = rem >> 7, k = rem & 127;
        g_uw1t[idx] = __float2half(uw1[l * HID * HID + k * HID + n]);
    } else if (idx < 196608) {                // uw2t permuted
        int j = idx - 98304;
        int l = j >> 14, rem = j & 16383, n = rem >> 7, k = rem & 127;
        g_uw2t[j] = __float2half(uw2[l * HID * HID + k * HID + permL(n)]);
    } else if (idx < 212992) {                // ow1t natural
        int j = idx - 196608, n = j >> 7, k = j & 127;
        g_ow1t[j] = __float2half(ow1[k * HID + n]);
    } else if (idx < 229376) {                // ow2t permuted
        int j = idx - 212992, n = j >> 7, k = j & 127;
        g_ow2t[j] = __float2half(ow2[k * HID + permL(n)]);
    } else if (idx < 229376 + N_NODES) {      // invdeg
        int n = idx - 229376;
        g_deg[n] = 1.0f / fmaxf(g_deg[n], 1.0f);
    }
}

// ================= LUT edge kernel: gather-lerp-scatter, no smem, no barriers ===========
// warp handles 8 consecutive edges (4 iters x 2). Lane owns channels [4*lane, 4*lane+4).
__global__ void __launch_bounds__(256) k_edge_lut(
    const int* __restrict__ gI, const int* __restrict__ gJ,
    const float* __restrict__ lut)
{
    const int gw = (blockIdx.x * 256 + threadIdx.x) >> 5;
    const int lane = threadIdx.x & 31;
    const int c4 = lane * 4;
    const int e0 = gw * 8;

#pragma unroll 1
    for (int it = 0; it < 4; it++) {
        const int e = e0 + it * 2;
        const float2 dv = *(const float2*)(g_d + e);
        const int2 iv = *(const int2*)(gI + e);
        const int2 jv = *(const int2*)(gJ + e);

        float uA = fminf(dv.x * INV_STEP, (float)(NK - 1));
        float uB = fminf(dv.y * INV_STEP, (float)(NK - 1));
        int iA = min((int)uA, NK - 2);
        int iB = min((int)uB, NK - 2);
        float fA = uA - (float)iA;
        float fB = uB - (float)iB;

        // issue all loads first (MLP)
        const float4 a0 = __ldg((const float4*)(lut + (size_t)iA * HID + c4));
        const float4 a1 = __ldg((const float4*)(lut + (size_t)(iA + 1) * HID + c4));
        const float4 b0 = __ldg((const float4*)(lut + (size_t)iB * HID + c4));
        const float4 b1 = __ldg((const float4*)(lut + (size_t)(iB + 1) * HID + c4));
        const uint2 hA = *(const uint2*)(g_hh + (size_t)jv.x * HID + c4);
        const uint2 hB = *(const uint2*)(g_hh + (size_t)jv.y * HID + c4);

        // edge A: m = lerp(W) * h[jA] -> red into aggr[iA]
        {
            float2 h0 = __half22float2(*(const __half2*)&hA.x);
            float2 h1 = __half22float2(*(const __half2*)&hA.y);
            float w0 = fmaf(fA, a1.x - a0.x, a0.x);
            float w1 = fmaf(fA, a1.y - a0.y, a0.y);
            float w2 = fmaf(fA, a1.z - a0.z, a0.z);
            float w3 = fmaf(fA, a1.w - a0.w, a0.w);
            red4(g_aggr + (size_t)iv.x * HID + c4,
                 w0 * h0.x, w1 * h0.y, w2 * h1.x, w3 * h1.y);
        }
        // edge B
        {
            float2 h0 = __half22float2(*(const __half2*)&hB.x);
            float2 h1 = __half22float2(*(const __half2*)&hB.y);
            float w0 = fmaf(fB, b1.x - b0.x, b0.x);
            float w1 = fmaf(fB, b1.y - b0.y, b0.y);
            float w2 = fmaf(fB, b1.z - b0.z, b0.z);
            float w3 = fmaf(fB, b1.w - b0.w, b0.w);
            red4(g_aggr + (size_t)iv.y * HID + c4,
                 w0 * h0.x, w1 * h0.y, w2 * h1.x, w3 * h1.y);
        }
    }
}

// ================= HMMA fused node update (proven, unchanged) =================
#define NOD_W1   0
#define NOD_W2   34816
#define NOD_A    69632
#define NOD_B1   104448
#define NOD_B2   104960
#define NOD_SMEM 105472

__global__ void __launch_bounds__(256, 2) k_node(
    const __half* __restrict__ uw1t, const __half* __restrict__ uw2t,
    const float* __restrict__ ub1, const float* __restrict__ ub2)
{
    extern __shared__ char sm[];
    const uint32_t sbase = smem_u32(sm);
    const int tid = threadIdx.x;
    const int lane = tid & 31, w = tid >> 5;
    const int r0 = blockIdx.x * 128;

    {
        const uint32_t* gw1 = (const uint32_t*)uw1t;
        const uint32_t* gw2 = (const uint32_t*)uw2t;
#pragma unroll
        for (int t = 0; t < 32; t++) {
            int word = tid + 256 * t;
            int row = word >> 6, c = word & 63;
            *(uint32_t*)(sm + NOD_W1 + row * 272 + c * 4) = gw1[word];
            *(uint32_t*)(sm + NOD_W2 + row * 272 + c * 4) = gw2[word];
        }
        if (tid < 128) {
            ((float*)(sm + NOD_B1))[tid] = ub1[tid];
            ((float*)(sm + NOD_B2))[tid] = ub2[tid];
        }
        const float4 z4 = make_float4(0.f, 0.f, 0.f, 0.f);
#pragma unroll
        for (int t = 0; t < 16; t++) {
            int idx = tid + 256 * t;
            int row = idx >> 5, c = idx & 31;
            int r = r0 + row;
            float s = 0.0f;
            float4 v = z4;
            if (r < N_NODES) {
                s = g_deg[r];
                v = ((const float4*)g_aggr)[(size_t)r * 32 + c];
                ((float4*)g_aggr)[(size_t)r * 32 + c] = z4;
            }
            __half2 a = __floats2half2_rn(v.x * s, v.y * s);
            __half2 b = __floats2half2_rn(v.z * s, v.w * s);
            uint2 pk = make_uint2(*(uint32_t*)&a, *(uint32_t*)&b);
            *(uint2*)(sm + NOD_A + row * 272 + c * 8) = pk;
        }
    }
    __syncthreads();

    const int erow0 = (w >> 2) * 64;
    const int nbase = (w & 3) * 32;
    const int rlo = lane >> 2;
    const int tq = lane & 3;
    const float* s_b1 = (const float*)(sm + NOD_B1);
    const float* s_b2 = (const float*)(sm + NOD_B2);
    const int cb = nbase + tq * 8;

    const int lrA = (lane & 7) + ((lane >> 3) & 1) * 8;
    const int caA = ((lane >> 4) & 1) * 16;
    const int lrB = (lane & 7) + ((lane >> 4) & 1) * 8;
    const int caB = ((lane >> 3) & 1) * 16;
    const uint32_t aBase  = sbase + NOD_A  + (erow0 + lrA) * 272 + caA;
    const uint32_t b1Base = sbase + NOD_W1 + (nbase + lrB) * 272 + caB;
    const uint32_t b2Base = sbase + NOD_W2 + (nbase + lrB) * 272 + caB;

    float acc[4][4][4];
    gemm_ldsm<272, 8>(aBase, b1Base, acc);
    __syncthreads();
    store_t_ssp(sm, NOD_A, acc, s_b1, erow0, nbase, rlo, tq);
    __syncthreads();
    gemm_ldsm<272, 8>(aBase, b2Base, acc);   // uw2t permuted

    float b2r[8];
#pragma unroll
    for (int q = 0; q < 8; q++) b2r[q] = s_b2[cb + q];

#pragma unroll
    for (int mi = 0; mi < 4; mi++) {
        int rA = r0 + erow0 + mi * 16 + rlo;
        int rB = rA + 8;
        if (rA < N_NODES) {
            uint4 o;
            __half2 h0 = __floats2half2_rn(acc[mi][0][0] + b2r[0], acc[mi][0][1] + b2r[1]);
            __half2 h1 = __floats2half2_rn(acc[mi][1][0] + b2r[2], acc[mi][1][1] + b2r[3]);
            __half2 h2 = __floats2half2_rn(acc[mi][2][0] + b2r[4], acc[mi][2][1] + b2r[5]);
            __half2 h3 = __floats2half2_rn(acc[mi][3][0] + b2r[6], acc[mi][3][1] + b2r[7]);
            o.x = *(uint32_t*)&h0; o.y = *(uint32_t*)&h1;
            o.z = *(uint32_t*)&h2; o.w = *(uint32_t*)&h3;
            *(uint4*)(g_hh + (size_t)rA * HID + cb) = o;
        }
        if (rB < N_NODES) {
            uint4 o;
            __half2 h0 = __floats2half2_rn(acc[mi][0][2] + b2r[0], acc[mi][0][3] + b2r[1]);
            __half2 h1 = __floats2half2_rn(acc[mi][1][2] + b2r[2], acc[mi][1][3] + b2r[3]);
            __half2 h2 = __floats2half2_rn(acc[mi][2][2] + b2r[4], acc[mi][2][3] + b2r[5]);
            __half2 h3 = __floats2half2_rn(acc[mi][3][2] + b2r[6], acc[mi][3][3] + b2r[7]);
            o.x = *(uint32_t*)&h0; o.y = *(uint32_t*)&h1;
            o.z = *(uint32_t*)&h2; o.w = *(uint32_t*)&h3;
            *(uint4*)(g_hh + (size_t)rB * HID + cb) = o;
        }
    }
}

// ================= HMMA fused output block + per-graph energy =================
#define OUT_W3   105472
#define OUT_SMEM 105984

__global__ void __launch_bounds__(256, 2) k_out(
    const __half* __restrict__ ow1t, const __half* __restrict__ ow2t,
    const float* __restrict__ ob1, const float* __restrict__ ob2,
    const float* __restrict__ ow3, const float* __restrict__ ob3,
    const int* __restrict__ batch, float* __restrict__ out)
{
    extern __shared__ char sm[];
    const uint32_t sbase = smem_u32(sm);
    const int tid = threadIdx.x;
    const int lane = tid & 31, w = tid >> 5;
    const int r0 = blockIdx.x * 128;

    {
        const uint32_t* gw1 = (const uint32_t*)ow1t;
        const uint32_t* gw2 = (const uint32_t*)ow2t;
#pragma unroll
        for (int t = 0; t < 32; t++) {
            int word = tid + 256 * t;
            int row = word >> 6, c = word & 63;
            *(uint32_t*)(sm + NOD_W1 + row * 272 + c * 4) = gw1[word];
            *(uint32_t*)(sm + NOD_W2 + row * 272 + c * 4) = gw2[word];
        }
        if (tid < 128) {
            ((float*)(sm + NOD_B1))[tid] = ob1[tid];
            ((float*)(sm + NOD_B2))[tid] = ob2[tid];
            ((float*)(sm + OUT_W3))[tid] = ow3[tid];
        }
        const uint32_t* gh = (const uint32_t*)g_hh;
#pragma unroll
        for (int t = 0; t < 32; t++) {
            int idx = tid + 256 * t;
            int row = idx >> 6, c = idx & 63;
            int r = r0 + row;
            uint32_t v = (r < N_NODES) ? gh[(size_t)r * 64 + c] : 0u;
            *(uint32_t*)(sm + NOD_A + row * 272 + c * 4) = v;
        }
    }
    __syncthreads();

    const int erow0 = (w >> 2) * 64;
    const int nbase = (w & 3) * 32;
    const int rlo = lane >> 2;
    const int tq = lane & 3;
    const float* s_b1 = (const float*)(sm + NOD_B1);
    const float* s_b2 = (const float*)(sm + NOD_B2);
    const float* s_w3 = (const float*)(sm + OUT_W3);
    const int cb = nbase + tq * 8;

    const int lrA = (lane & 7) + ((lane >> 3) & 1) * 8;
    const int caA = ((lane >> 4) & 1) * 16;
    const int lrB = (lane & 7) + ((lane >> 4) & 1) * 8;
    const int caB = ((lane >> 3) & 1) * 16;
    const uint32_t aBase  = sbase + NOD_A  + (erow0 + lrA) * 272 + caA;
    const uint32_t b1Base = sbase + NOD_W1 + (nbase + lrB) * 272 + caB;
    const uint32_t b2Base = sbase + NOD_W2 + (nbase + lrB) * 272 + caB;

    float acc[4][4][4];
    gemm_ldsm<272, 8>(aBase, b1Base, acc);
    __syncthreads();
    store_t_ssp(sm, NOD_A, acc, s_b1, erow0, nbase, rlo, tq);
    __syncthreads();
    gemm_ldsm<272, 8>(aBase, b2Base, acc);   // ow2t permuted

    float p0[4], p1[4];
#pragma unroll
    for (int mi = 0; mi < 4; mi++) {
        p0[mi] = 0.0f; p1[mi] = 0.0f;
#pragma unroll
        for (int ni = 0; ni < 4; ni++) {
            int col = cb + ni * 2;
            float b0 = s_b2[col], b1 = s_b2[col + 1];
            float w0 = s_w3[col], w1 = s_w3[col + 1];
            p0[mi] += sspf(acc[mi][ni][0] + b0) * w0 + sspf(acc[mi][ni][1] + b1) * w1;
            p1[mi] += sspf(acc[mi][ni][2] + b0) * w0 + sspf(acc[mi][ni][3] + b1) * w1;
        }
        p0[mi] += __shfl_xor_sync(0xffffffffu, p0[mi], 1);
        p0[mi] += __shfl_xor_sync(0xffffffffu, p0[mi], 2);
        p1[mi] += __shfl_xor_sync(0xffffffffu, p1[mi], 1);
        p1[mi] += __shfl_xor_sync(0xffffffffu, p1[mi], 2);
    }
    __syncthreads();
    float* s_part = (float*)(sm + NOD_A);
    if (tq == 0) {
#pragma unroll
        for (int mi = 0; mi < 4; mi++) {
            int r = erow0 + mi * 16 + rlo;
            s_part[r * 4 + (w & 3)] = p0[mi];
            s_part[(r + 8) * 4 + (w & 3)] = p1[mi];
        }
    }
    __syncthreads();
    if (tid < 128) {
        int r = r0 + tid;
        if (r < N_NODES) {
            float e = s_part[tid * 4] + s_part[tid * 4 + 1] +
                      s_part[tid * 4 + 2] + s_part[tid * 4 + 3] + ob3[0];
            atomicAdd(&out[batch[r]], e);
        }
    }
}

// ================= launcher =================
extern "C" void kernel_launch(void* const* d_in, const int* in_sizes, int n_in,
                              void* d_out, int out_size)
{
    const int*   z     = (const int*)d_in[0];
    const float* pos   = (const float*)d_in[1];
    const int*   ei    = (const int*)d_in[2];
    const int*   batch = (const int*)d_in[3];
    const float* embed = (const float*)d_in[4];
    const float* fw1   = (const float*)d_in[5];
    const float* fb1   = (const float*)d_in[6];
    const float* fw2   = (const float*)d_in[7];
    const float* fb2   = (const float*)d_in[8];
    const float* uw1   = (const float*)d_in[9];
    const float* ub1   = (const float*)d_in[10];
    const float* uw2   = (const float*)d_in[11];
    const float* ub2   = (const float*)d_in[12];
    const float* ow1   = (const float*)d_in[13];
    const float* ob1   = (const float*)d_in[14];
    const float* ow2   = (const float*)d_in[15];
    const float* ob2   = (const float*)d_in[16];
    const float* ow3   = (const float*)d_in[17];
    const float* ob3   = (const float*)d_in[18];
    float* out = (float*)d_out;

    const int* gI = ei;
    const int* gJ = ei + N_EDGES;

    cudaFuncSetAttribute(k_node, cudaFuncAttributeMaxDynamicSharedMemorySize, NOD_SMEM);
    cudaFuncSetAttribute(k_out,  cudaFuncAttributeMaxDynamicSharedMemorySize, OUT_SMEM);

    float* p_lut;
    __half *p_uw1t, *p_uw2t, *p_ow1t, *p_ow2t;
    cudaGetSymbolAddress((void**)&p_lut,  g_lut);
    cudaGetSymbolAddress((void**)&p_uw1t, g_uw1t);
    cudaGetSymbolAddress((void**)&p_uw2t, g_uw2t);
    cudaGetSymbolAddress((void**)&p_ow1t, g_ow1t);
    cudaGetSymbolAddress((void**)&p_ow2t, g_ow2t);

    // exactly 3 setup launches -> first k_edge_lut is launch #4 (ncu profiles #4)
    k_setup<<<(N_NODES * HID + 255) / 256, 256>>>(z, embed, out);
    k_dist<<<(N_EDGES + 255) / 256, 256>>>(gI, gJ, pos);
    k_prep<<<LUT_BLOCKS + PREP_BLOCKS, 128>>>(fw1, fb1, fw2, fb2, uw1, uw2, ow1, ow2);

    const int node_grid = (N_NODES + 127) / 128;
    const int edge_grid = N_EDGES / (8 * 8);   // 8 warps/block x 8 edges/warp = 12500

    for (int l = 0; l < NLAYERS; l++) {
        k_edge_lut<<<edge_grid, 256>>>(gI, gJ, p_lut + (size_t)l * NK * HID);
        k_node<<<node_grid, 256, NOD_SMEM>>>(
            p_uw1t + (size_t)l * HID * HID, p_uw2t + (size_t)l * HID * HID,
            ub1 + (size_t)l * HID, ub2 + (size_t)l * HID);
    }

    k_out<<<node_grid, 256, OUT_SMEM>>>(p_ow1t, p_ow2t, ob1, ob2, ow3, ob3, batch, out);
}

// round 16
// speedup vs baseline: 1.0347x; 1.0347x over previous
#include <cuda_runtime.h>
#include <cuda_fp16.h>
#include <math.h>
#include <stdint.h>

#define N_NODES  50000
#define N_EDGES  800000
#define N_GRAPHS 512
#define HID      128
#define RBF      32
#define NLAYERS  6
#define GAMMA    32.0f

// LUT parameters: W(d) sampled on [0, SPAN], clamped above (rbf ~ 0 beyond)
#define NK       2048
#define SPAN     6.4f
#define LSTEP    (SPAN / (NK - 1))
#define INV_STEP ((NK - 1) / SPAN)

// ================= scratch (static device globals; no allocation) =================
__device__ __align__(16) __half g_hh[(size_t)N_NODES * HID];     // node features fp16
__device__ float g_aggr[(size_t)N_NODES * HID];
__device__ float g_deg[N_NODES];
__device__ __align__(16) float4 g_er[N_EDGES];                   // {u, i, j, 0} packed records
__device__ __align__(16) __half g_luth[NLAYERS * NK * HID];      // 3.1 MB fp16 W(d) tables
__device__ __align__(16) __half g_uw1t[NLAYERS * HID * HID];
__device__ __align__(16) __half g_uw2t[NLAYERS * HID * HID];     // rows PERMUTED
__device__ __align__(16) __half g_ow1t[HID * HID];
__device__ __align__(16) __half g_ow2t[HID * HID];               // rows PERMUTED

// permutation of second-GEMM B rows within each 32-block:
// physical row (ni*8 + tq*2 + b) holds logical channel (tq*8 + ni*2 + b)
__host__ __device__ __forceinline__ int permL(int n) {
    return (n & ~31) | ((((n >> 1) & 3) << 3) | (((n >> 3) & 3) << 1) | (n & 1));
}

// ================= helpers =================
__device__ __forceinline__ float sspf(float x) {
    return fmaxf(x, 0.0f) + __logf(1.0f + __expf(-fabsf(x))) - 0.5f;
}
__device__ __forceinline__ void red4(float* p, float a, float b, float c, float d) {
    asm volatile("red.global.add.v4.f32 [%0], {%1,%2,%3,%4};"
                 :: "l"(p), "f"(a), "f"(b), "f"(c), "f"(d) : "memory");
}
__device__ __forceinline__ void mma16816(float c[4], uint32_t a0, uint32_t a1,
                                         uint32_t a2, uint32_t a3,
                                         uint32_t b0, uint32_t b1) {
    asm volatile(
        "mma.sync.aligned.m16n8k16.row.col.f32.f16.f16.f32 "
        "{%0,%1,%2,%3}, {%4,%5,%6,%7}, {%8,%9}, {%0,%1,%2,%3};"
        : "+f"(c[0]), "+f"(c[1]), "+f"(c[2]), "+f"(c[3])
        : "r"(a0), "r"(a1), "r"(a2), "r"(a3), "r"(b0), "r"(b1));
}
__device__ __forceinline__ void ldsm_x4(uint32_t (&r)[4], uint32_t addr) {
    asm volatile("ldmatrix.sync.aligned.m8n8.x4.shared.b16 {%0,%1,%2,%3}, [%4];"
                 : "=r"(r[0]), "=r"(r[1]), "=r"(r[2]), "=r"(r[3]) : "r"(addr));
}
__device__ __forceinline__ uint32_t smem_u32(const void* p) {
    uint32_t a;
    asm("{ .reg .u64 t; cvta.to.shared.u64 t, %1; cvt.u32.u64 %0, t; }" : "=r"(a) : "l"(p));
    return a;
}

template<int STRIDE, int NKT>
__device__ __forceinline__ void gemm_ldsm(uint32_t aBase, uint32_t bBase,
                                          float (&acc)[4][4][4])
{
#pragma unroll
    for (int mi = 0; mi < 4; mi++)
#pragma unroll
        for (int ni = 0; ni < 4; ni++)
#pragma unroll
            for (int q = 0; q < 4; q++) acc[mi][ni][q] = 0.0f;
#pragma unroll
    for (int kt = 0; kt < NKT; kt++) {
        const int kb = kt * 32;
        uint32_t B[2][4];
        ldsm_x4(B[0], bBase + kb);
        ldsm_x4(B[1], bBase + 16 * STRIDE + kb);
        uint32_t A[4][4];
#pragma unroll
        for (int mi = 0; mi < 4; mi++)
            ldsm_x4(A[mi], aBase + mi * 16 * STRIDE + kb);
#pragma unroll
        for (int mi = 0; mi < 4; mi++)
#pragma unroll
            for (int ni = 0; ni < 4; ni++)
                mma16816(acc[mi][ni], A[mi][0], A[mi][1], A[mi][2], A[mi][3],
                         B[ni >> 1][(ni & 1) * 2], B[ni >> 1][(ni & 1) * 2 + 1]);
    }
}

__device__ __forceinline__ void store_t_ssp(char* sm, int offT,
                                            const float (&acc)[4][4][4],
                                            const float* s_b,
                                            int erow0, int nbase, int rlo, int tq)
{
#pragma unroll
    for (int mi = 0; mi < 4; mi++) {
        int r = erow0 + mi * 16 + rlo;
#pragma unroll
        for (int ni = 0; ni < 4; ni++) {
            int col = nbase + ni * 8 + tq * 2;
            float b0 = s_b[col], b1 = s_b[col + 1];
            __half2 lo = __floats2half2_rn(sspf(acc[mi][ni][0] + b0),
                                           sspf(acc[mi][ni][1] + b1));
            __half2 hi = __floats2half2_rn(sspf(acc[mi][ni][2] + b0),
                                           sspf(acc[mi][ni][3] + b1));
            *(__half2*)(sm + offT + r * 272 + col * 2) = lo;
            *(__half2*)(sm + offT + (r + 8) * 272 + col * 2) = hi;
        }
    }
}

// ================= setup (exactly 3 launches before first edge kernel) =================
// launch 1: h init + zero aggr/deg/out
__global__ void k_setup(const int* __restrict__ z, const float* __restrict__ embed,
                        float* __restrict__ out) {
    int idx = blockIdx.x * blockDim.x + threadIdx.x;
    if (idx < N_NODES * HID) {
        int n = idx >> 7, c = idx & 127;
        g_hh[idx] = __float2half(embed[z[n] * HID + c]);
        g_aggr[idx] = 0.0f;
    }
    if (idx < N_NODES) g_deg[idx] = 0.0f;
    if (idx < N_GRAPHS) out[idx] = 0.0f;
}

// launch 2: packed edge records {u, i, j} + degree count
__global__ void k_dist(const int* __restrict__ gI, const int* __restrict__ gJ,
                       const float* __restrict__ pos) {
    int e = blockIdx.x * blockDim.x + threadIdx.x;
    if (e >= N_EDGES) return;
    int i = gI[e], j = gJ[e];
    float dx = pos[i * 3 + 0] - pos[j * 3 + 0];
    float dy = pos[i * 3 + 1] - pos[j * 3 + 1];
    float dz = pos[i * 3 + 2] - pos[j * 3 + 2];
    float d = sqrtf(dx * dx + dy * dy + dz * dz);
    float u = fminf(d * INV_STEP, (float)(NK - 1));
    g_er[e] = make_float4(u, __int_as_float(i), __int_as_float(j), 0.0f);
    atomicAdd(&g_deg[i], 1.0f);
}

// launch 3: fp16 LUT build (blocks 0..767) + node/output weight prep + invdeg (rest)
#define LUT_BLOCKS 768      // 6 layers x 128 blocks x 16 knots
#define PREP_TOTAL (98304 * 2 + 16384 * 2 + N_NODES)   // 279376
#define PREP_BLOCKS ((PREP_TOTAL + 127) / 128)         // 2183

__global__ void k_prep(const float* __restrict__ fw1, const float* __restrict__ fb1,
                       const float* __restrict__ fw2, const float* __restrict__ fb2,
                       const float* __restrict__ uw1, const float* __restrict__ uw2,
                       const float* __restrict__ ow1, const float* __restrict__ ow2) {
    const int b = blockIdx.x;
    const int tid = threadIdx.x;
    if (b < LUT_BLOCKS) {
        const int l = b >> 7;                 // layer
        const int kb = (b & 127) * 16;        // first knot of this block
        __shared__ float s_rbf[32];
        __shared__ float s_t[128];
        for (int kk = 0; kk < 16; kk++) {
            const int knot = kb + kk;
            const float d = knot * LSTEP;
            if (tid < 32) {
                float u = d - tid * (4.0f / 31.0f);
                s_rbf[tid] = expf(-GAMMA * u * u);
            }
            __syncthreads();
            float acc = fb1[l * HID + tid];
            for (int k2 = 0; k2 < RBF; k2++)
                acc = fmaf(s_rbf[k2], fw1[l * RBF * HID + k2 * HID + tid], acc);
            s_t[tid] = sspf(acc);
            __syncthreads();
            float wv = fb2[l * HID + tid];
            for (int j = 0; j < HID; j++)
                wv = fmaf(s_t[j], fw2[l * HID * HID + j * HID + tid], wv);
            g_luth[((size_t)l * NK + knot) * HID + tid] = __float2half(wv);
            __syncthreads();
        }
        return;
    }
    int idx = (b - LUT_BLOCKS) * 128 + tid;
    if (idx < 98304) {                        // uw1t natural
        int l = idx >> 14, rem = idx & 16383, n = rem >> 7, k = rem & 127;
        g_uw1t[idx] = __float2half(uw1[l * HID * HID + k * HID + n]);
    } else if (idx < 196608) {                // uw2t permuted
        int j = idx - 98304;
        int l = j >> 14, rem = j & 16383, n = rem >> 7, k = rem & 127;
        g_uw2t[j] = __float2half(uw2[l * HID * HID + k * HID + permL(n)]);
    } else if (idx < 212992) {                // ow1t natural
        int j = idx - 196608, n = j >> 7, k = j & 127;
        g_ow1t[j] = __float2half(ow1[k * HID + n]);
    } else if (idx < 229376) {                // ow2t permuted
        int j = idx - 212992, n = j >> 7, k = j & 127;
        g_ow2t[j] = __float2half(ow2[k * HID + permL(n)]);
    } else if (idx < 229376 + N_NODES) {      // invdeg
        int n = idx - 229376;
        g_deg[n] = 1.0f / fmaxf(g_deg[n], 1.0f);
    }
}

// ================= LUT edge kernel: gather-lerp-scatter, no smem, no barriers ===========
// warp handles 8 consecutive edges (4 iters x 2). Lane owns channels [4*lane, 4*lane+4).
// fp16 LUT rows; lower row load predicated off when fA==1 (clamped edges, warp-uniform).
__global__ void __launch_bounds__(256) k_edge_lut(const __half* __restrict__ luth)
{
    const int gw = (blockIdx.x * 256 + threadIdx.x) >> 5;
    const int lane = threadIdx.x & 31;
    const int c4 = lane * 4;
    const int e0 = gw * 8;

#pragma unroll 1
    for (int it = 0; it < 4; it++) {
        const int e = e0 + it * 2;
        const float4 recA = g_er[e];       // uniform 16B
        const float4 recB = g_er[e + 1];

        const float uA = recA.x;
        const int iiA = __float_as_int(recA.y), jA = __float_as_int(recA.z);
        const int iA = min((int)uA, NK - 2);
        const float fA = uA - (float)iA;

        const float uB = recB.x;
        const int iiB = __float_as_int(recB.y), jB = __float_as_int(recB.z);
        const int iB = min((int)uB, NK - 2);
        const float fB = uB - (float)iB;

        // LUT loads (fp16 rows, 8B/lane); skip lower row when fully clamped
        const __half* lrA = luth + (size_t)iA * HID + c4;
        const __half* lrB = luth + (size_t)iB * HID + c4;
        uint2 a1 = *(const uint2*)(lrA + HID);
        uint2 a0; if (fA < 1.0f) a0 = *(const uint2*)lrA; else a0 = a1;
        uint2 b1 = *(const uint2*)(lrB + HID);
        uint2 b0; if (fB < 1.0f) b0 = *(const uint2*)lrB; else b0 = b1;
        const uint2 hA = *(const uint2*)(g_hh + (size_t)jA * HID + c4);
        const uint2 hB = *(const uint2*)(g_hh + (size_t)jB * HID + c4);

        // edge A: m = lerp(W) * h[jA] -> red into aggr[iA]
        {
            float2 w0p = __half22float2(*(const __half2*)&a0.x);
            float2 w0q = __half22float2(*(const __half2*)&a0.y);
            float2 w1p = __half22float2(*(const __half2*)&a1.x);
            float2 w1q = __half22float2(*(const __half2*)&a1.y);
            float2 h0 = __half22float2(*(const __half2*)&hA.x);
            float2 h1 = __half22float2(*(const __half2*)&hA.y);
            float w0 = fmaf(fA, w1p.x - w0p.x, w0p.x);
            float w1 = fmaf(fA, w1p.y - w0p.y, w0p.y);
            float w2 = fmaf(fA, w1q.x - w0q.x, w0q.x);
            float w3 = fmaf(fA, w1q.y - w0q.y, w0q.y);
            red4(g_aggr + (size_t)iiA * HID + c4,
                 w0 * h0.x, w1 * h0.y, w2 * h1.x, w3 * h1.y);
        }
        // edge B
        {
            float2 w0p = __half22float2(*(const __half2*)&b0.x);
            float2 w0q = __half22float2(*(const __half2*)&b0.y);
            float2 w1p = __half22float2(*(const __half2*)&b1.x);
            float2 w1q = __half22float2(*(const __half2*)&b1.y);
            float2 h0 = __half22float2(*(const __half2*)&hB.x);
            float2 h1 = __half22float2(*(const __half2*)&hB.y);
            float w0 = fmaf(fB, w1p.x - w0p.x, w0p.x);
            float w1 = fmaf(fB, w1p.y - w0p.y, w0p.y);
            float w2 = fmaf(fB, w1q.x - w0q.x, w0q.x);
            float w3 = fmaf(fB, w1q.y - w0q.y, w0q.y);
            red4(g_aggr + (size_t)iiB * HID + c4,
                 w0 * h0.x, w1 * h0.y, w2 * h1.x, w3 * h1.y);
        }
    }
}

// ================= HMMA fused node update (proven, unchanged) =================
#define NOD_W1   0
#define NOD_W2   34816
#define NOD_A    69632
#define NOD_B1   104448
#define NOD_B2   104960
#define NOD_SMEM 105472

__global__ void __launch_bounds__(256, 2) k_node(
    const __half* __restrict__ uw1t, const __half* __restrict__ uw2t,
    const float* __restrict__ ub1, const float* __restrict__ ub2)
{
    extern __shared__ char sm[];
    const uint32_t sbase = smem_u32(sm);
    const int tid = threadIdx.x;
    const int lane = tid & 31, w = tid >> 5;
    const int r0 = blockIdx.x * 128;

    {
        const uint32_t* gw1 = (const uint32_t*)uw1t;
        const uint32_t* gw2 = (const uint32_t*)uw2t;
#pragma unroll
        for (int t = 0; t < 32; t++) {
            int word = tid + 256 * t;
            int row = word >> 6, c = word & 63;
            *(uint32_t*)(sm + NOD_W1 + row * 272 + c * 4) = gw1[word];
            *(uint32_t*)(sm + NOD_W2 + row * 272 + c * 4) = gw2[word];
        }
        if (tid < 128) {
            ((float*)(sm + NOD_B1))[tid] = ub1[tid];
            ((float*)(sm + NOD_B2))[tid] = ub2[tid];
        }
        const float4 z4 = make_float4(0.f, 0.f, 0.f, 0.f);
#pragma unroll
        for (int t = 0; t < 16; t++) {
            int idx = tid + 256 * t;
            int row = idx >> 5, c = idx & 31;
            int r = r0 + row;
            float s = 0.0f;
            float4 v = z4;
            if (r < N_NODES) {
                s = g_deg[r];
                v = ((const float4*)g_aggr)[(size_t)r * 32 + c];
                ((float4*)g_aggr)[(size_t)r * 32 + c] = z4;
            }
            __half2 a = __floats2half2_rn(v.x * s, v.y * s);
            __half2 b = __floats2half2_rn(v.z * s, v.w * s);
            uint2 pk = make_uint2(*(uint32_t*)&a, *(uint32_t*)&b);
            *(uint2*)(sm + NOD_A + row * 272 + c * 8) = pk;
        }
    }
    __syncthreads();

    const int erow0 = (w >> 2) * 64;
    const int nbase = (w & 3) * 32;
    const int rlo = lane >> 2;
    const int tq = lane & 3;
    const float* s_b1 = (const float*)(sm + NOD_B1);
    const float* s_b2 = (const float*)(sm + NOD_B2);
    const int cb = nbase + tq * 8;

    const int lrA = (lane & 7) + ((lane >> 3) & 1) * 8;
    const int caA = ((lane >> 4) & 1) * 16;
    const int lrB = (lane & 7) + ((lane >> 4) & 1) * 8;
    const int caB = ((lane >> 3) & 1) * 16;
    const uint32_t aBase  = sbase + NOD_A  + (erow0 + lrA) * 272 + caA;
    const uint32_t b1Base = sbase + NOD_W1 + (nbase + lrB) * 272 + caB;
    const uint32_t b2Base = sbase + NOD_W2 + (nbase + lrB) * 272 + caB;

    float acc[4][4][4];
    gemm_ldsm<272, 8>(aBase, b1Base, acc);
    __syncthreads();
    store_t_ssp(sm, NOD_A, acc, s_b1, erow0, nbase, rlo, tq);
    __syncthreads();
    gemm_ldsm<272, 8>(aBase, b2Base, acc);   // uw2t permuted

    float b2r[8];
#pragma unroll
    for (int q = 0; q < 8; q++) b2r[q] = s_b2[cb + q];

#pragma unroll
    for (int mi = 0; mi < 4; mi++) {
        int rA = r0 + erow0 + mi * 16 + rlo;
        int rB = rA + 8;
        if (rA < N_NODES) {
            uint4 o;
            __half2 h0 = __floats2half2_rn(acc[mi][0][0] + b2r[0], acc[mi][0][1] + b2r[1]);
            __half2 h1 = __floats2half2_rn(acc[mi][1][0] + b2r[2], acc[mi][1][1] + b2r[3]);
            __half2 h2 = __floats2half2_rn(acc[mi][2][0] + b2r[4], acc[mi][2][1] + b2r[5]);
            __half2 h3 = __floats2half2_rn(acc[mi][3][0] + b2r[6], acc[mi][3][1] + b2r[7]);
            o.x = *(uint32_t*)&h0; o.y = *(uint32_t*)&h1;
            o.z = *(uint32_t*)&h2; o.w = *(uint32_t*)&h3;
            *(uint4*)(g_hh + (size_t)rA * HID + cb) = o;
        }
        if (rB < N_NODES) {
            uint4 o;
            __half2 h0 = __floats2half2_rn(acc[mi][0][2] + b2r[0], acc[mi][0][3] + b2r[1]);
            __half2 h1 = __floats2half2_rn(acc[mi][1][2] + b2r[2], acc[mi][1][3] + b2r[3]);
            __half2 h2 = __floats2half2_rn(acc[mi][2][2] + b2r[4], acc[mi][2][3] + b2r[5]);
            __half2 h3 = __floats2half2_rn(acc[mi][3][2] + b2r[6], acc[mi][3][3] + b2r[7]);
            o.x = *(uint32_t*)&h0; o.y = *(uint32_t*)&h1;
            o.z = *(uint32_t*)&h2; o.w = *(uint32_t*)&h3;
            *(uint4*)(g_hh + (size_t)rB * HID + cb) = o;
        }
    }
}

// ================= HMMA fused output block + per-graph energy =================
#define OUT_W3   105472
#define OUT_SMEM 105984

__global__ void __launch_bounds__(256, 2) k_out(
    const __half* __restrict__ ow1t, const __half* __restrict__ ow2t,
    const float* __restrict__ ob1, const float* __restrict__ ob2,
    const float* __restrict__ ow3, const float* __restrict__ ob3,
    const int* __restrict__ batch, float* __restrict__ out)
{
    extern __shared__ char sm[];
    const uint32_t sbase = smem_u32(sm);
    const int tid = threadIdx.x;
    const int lane = tid & 31, w = tid >> 5;
    const int r0 = blockIdx.x * 128;

    {
        const uint32_t* gw1 = (const uint32_t*)ow1t;
        const uint32_t* gw2 = (const uint32_t*)ow2t;
#pragma unroll
        for (int t = 0; t < 32; t++) {
            int word = tid + 256 * t;
            int row = word >> 6, c = word & 63;
            *(uint32_t*)(sm + NOD_W1 + row * 272 + c * 4) = gw1[word];
            *(uint32_t*)(sm + NOD_W2 + row * 272 + c * 4) = gw2[word];
        }
        if (tid < 128) {
            ((float*)(sm + NOD_B1))[tid] = ob1[tid];
            ((float*)(sm + NOD_B2))[tid] = ob2[tid];
            ((float*)(sm + OUT_W3))[tid] = ow3[tid];
        }
        const uint32_t* gh = (const uint32_t*)g_hh;
#pragma unroll
        for (int t = 0; t < 32; t++) {
            int idx = tid + 256 * t;
            int row = idx >> 6, c = idx & 63;
            int r = r0 + row;
            uint32_t v = (r < N_NODES) ? gh[(size_t)r * 64 + c] : 0u;
            *(uint32_t*)(sm + NOD_A + row * 272 + c * 4) = v;
        }
    }
    __syncthreads();

    const int erow0 = (w >> 2) * 64;
    const int nbase = (w & 3) * 32;
    const int rlo = lane >> 2;
    const int tq = lane & 3;
    const float* s_b1 = (const float*)(sm + NOD_B1);
    const float* s_b2 = (const float*)(sm + NOD_B2);
    const float* s_w3 = (const float*)(sm + OUT_W3);
    const int cb = nbase + tq * 8;

    const int lrA = (lane & 7) + ((lane >> 3) & 1) * 8;
    const int caA = ((lane >> 4) & 1) * 16;
    const int lrB = (lane & 7) + ((lane >> 4) & 1) * 8;
    const int caB = ((lane >> 3) & 1) * 16;
    const uint32_t aBase  = sbase + NOD_A  + (erow0 + lrA) * 272 + caA;
    const uint32_t b1Base = sbase + NOD_W1 + (nbase + lrB) * 272 + caB;
    const uint32_t b2Base = sbase + NOD_W2 + (nbase + lrB) * 272 + caB;

    float acc[4][4][4];
    gemm_ldsm<272, 8>(aBase, b1Base, acc);
    __syncthreads();
    store_t_ssp(sm, NOD_A, acc, s_b1, erow0, nbase, rlo, tq);
    __syncthreads();
    gemm_ldsm<272, 8>(aBase, b2Base, acc);   // ow2t permuted

    float p0[4], p1[4];
#pragma unroll
    for (int mi = 0; mi < 4; mi++) {
        p0[mi] = 0.0f; p1[mi] = 0.0f;
#pragma unroll
        for (int ni = 0; ni < 4; ni++) {
            int col = cb + ni * 2;
            float b0 = s_b2[col], b1 = s_b2[col + 1];
            float w0 = s_w3[col], w1 = s_w3[col + 1];
            p0[mi] += sspf(acc[mi][ni][0] + b0) * w0 + sspf(acc[mi][ni][1] + b1) * w1;
            p1[mi] += sspf(acc[mi][ni][2] + b0) * w0 + sspf(acc[mi][ni][3] + b1) * w1;
        }
        p0[mi] += __shfl_xor_sync(0xffffffffu, p0[mi], 1);
        p0[mi] += __shfl_xor_sync(0xffffffffu, p0[mi], 2);
        p1[mi] += __shfl_xor_sync(0xffffffffu, p1[mi], 1);
        p1[mi] += __shfl_xor_sync(0xffffffffu, p1[mi], 2);
    }
    __syncthreads();
    float* s_part = (float*)(sm + NOD_A);
    if (tq == 0) {
#pragma unroll
        for (int mi = 0; mi < 4; mi++) {
            int r = erow0 + mi * 16 + rlo;
            s_part[r * 4 + (w & 3)] = p0[mi];
            s_part[(r + 8) * 4 + (w & 3)] = p1[mi];
        }
    }
    __syncthreads();
    if (tid < 128) {
        int r = r0 + tid;
        if (r < N_NODES) {
            float e = s_part[tid * 4] + s_part[tid * 4 + 1] +
                      s_part[tid * 4 + 2] + s_part[tid * 4 + 3] + ob3[0];
            atomicAdd(&out[batch[r]], e);
        }
    }
}

// ================= launcher =================
extern "C" void kernel_launch(void* const* d_in, const int* in_sizes, int n_in,
                              void* d_out, int out_size)
{
    const int*   z     = (const int*)d_in[0];
    const float* pos   = (const float*)d_in[1];
    const int*   ei    = (const int*)d_in[2];
    const int*   batch = (const int*)d_in[3];
    const float* embed = (const float*)d_in[4];
    const float* fw1   = (const float*)d_in[5];
    const float* fb1   = (const float*)d_in[6];
    const float* fw2   = (const float*)d_in[7];
    const float* fb2   = (const float*)d_in[8];
    const float* uw1   = (const float*)d_in[9];
    const float* ub1   = (const float*)d_in[10];
    const float* uw2   = (const float*)d_in[11];
    const float* ub2   = (const float*)d_in[12];
    const float* ow1   = (const float*)d_in[13];
    const float* ob1   = (const float*)d_in[14];
    const float* ow2   = (const float*)d_in[15];
    const float* ob2   = (const float*)d_in[16];
    const float* ow3   = (const float*)d_in[17];
    const float* ob3   = (const float*)d_in[18];
    float* out = (float*)d_out;

    const int* gI = ei;
    const int* gJ = ei + N_EDGES;

    cudaFuncSetAttribute(k_node, cudaFuncAttributeMaxDynamicSharedMemorySize, NOD_SMEM);
    cudaFuncSetAttribute(k_out,  cudaFuncAttributeMaxDynamicSharedMemorySize, OUT_SMEM);

    __half* p_luth;
    __half *p_uw1t, *p_uw2t, *p_ow1t, *p_ow2t;
    cudaGetSymbolAddress((void**)&p_luth, g_luth);
    cudaGetSymbolAddress((void**)&p_uw1t, g_uw1t);
    cudaGetSymbolAddress((void**)&p_uw2t, g_uw2t);
    cudaGetSymbolAddress((void**)&p_ow1t, g_ow1t);
    cudaGetSymbolAddress((void**)&p_ow2t, g_ow2t);

    // exactly 3 setup launches -> first k_edge_lut is launch #4 (ncu profiles #4)
    k_setup<<<(N_NODES * HID + 255) / 256, 256>>>(z, embed, out);
    k_dist<<<(N_EDGES + 255) / 256, 256>>>(gI, gJ, pos);
    k_prep<<<LUT_BLOCKS + PREP_BLOCKS, 128>>>(fw1, fb1, fw2, fb2, uw1, uw2, ow1, ow2);

    const int node_grid = (N_NODES + 127) / 128;
    const int edge_grid = N_EDGES / (8 * 8);   // 8 warps/block x 8 edges/warp = 12500

    for (int l = 0; l < NLAYERS; l++) {
        k_edge_lut<<<edge_grid, 256>>>(p_luth + (size_t)l * NK * HID);
        k_node<<<node_grid, 256, NOD_SMEM>>>(
            p_uw1t + (size_t)l * HID * HID, p_uw2t + (size_t)l * HID * HID,
            ub1 + (size_t)l * HID, ub2 + (size_t)l * HID);
    }

    k_out<<<node_grid, 256, OUT_SMEM>>>(p_ow1t, p_ow2t, ob1, ob2, ow3, ob3, batch, out);
}